// round 15
// baseline (speedup 1.0000x reference)
#include <cuda_runtime.h>
#include <cuda_bf16.h>
#include <cstdint>

#define TT 131072
#define CD 256
#define MD 128
#define NB 1024
#define ATTN_OFF ((size_t)TT*2*CD)
#define NM_OFF (ATTN_OFF+(size_t)TT*MD)

// Resident chunk buffers (Q in phase1 / nm in phase2): 4 x [128x64 bf16 hi/lo], stride 144B.
// chunk k at k*36864 (hi at base, lo at +18432).
#define RES(k) ((uint32_t)(k) * 36864u)
// Stream buffers (mem in phase1 / Q in phase2): 2 buffers at:
#define SB0 147456u
#define SB1 184320u
// P tiles 128x128 bf16 stride 272B overlay the stream region:
#define PH_ 147456u
#define PL_ 182272u
#define SMX 221184
#define SSUM 223232
#define SMEMB 225280

__device__ float g_add_mem[MD*CD];
__device__ __nv_bfloat16 g_nm_h[MD*CD], g_nm_l[MD*CD];
__device__ __nv_bfloat16 g_m_h[MD*CD], g_m_l[MD*CD];
__device__ __nv_bfloat16 g_q_h[(size_t)TT*CD], g_q_l[(size_t)TT*CD];

__device__ __forceinline__ uint32_t smem_u32(const void* p) {
    uint32_t a;
    asm("{ .reg .u64 t; cvta.to.shared.u64 t, %1; cvt.u32.u64 %0, t; }" : "=r"(a) : "l"(p));
    return a;
}
#define LDM4(r, a) asm volatile("ldmatrix.sync.aligned.m8n8.x4.shared.b16 {%0,%1,%2,%3}, [%4];" \
    : "=r"((r)[0]),"=r"((r)[1]),"=r"((r)[2]),"=r"((r)[3]) : "r"(a))
#define LDM4T(r, a) asm volatile("ldmatrix.sync.aligned.m8n8.x4.trans.shared.b16 {%0,%1,%2,%3}, [%4];" \
    : "=r"((r)[0]),"=r"((r)[1]),"=r"((r)[2]),"=r"((r)[3]) : "r"(a))
#define MMA(d, a, b0, b1) asm volatile( \
    "mma.sync.aligned.m16n8k16.row.col.f32.bf16.bf16.f32 {%0,%1,%2,%3}, {%4,%5,%6,%7}, {%8,%9}, {%0,%1,%2,%3};" \
    : "+f"((d)[0]),"+f"((d)[1]),"+f"((d)[2]),"+f"((d)[3]) \
    : "r"((a)[0]),"r"((a)[1]),"r"((a)[2]),"r"((a)[3]), "r"(b0),"r"(b1))
#define CP_ASYNC(dst, src) asm volatile("cp.async.ca.shared.global [%0], [%1], 16;" :: "r"(dst), "l"(src) : "memory")
#define CP_COMMIT() asm volatile("cp.async.commit_group;" ::: "memory")
#define CP_WAIT1() asm volatile("cp.async.wait_group 1;" ::: "memory")
#define CP_WAIT0() asm volatile("cp.async.wait_group 0;" ::: "memory")

#define PKF2(res, a, b) asm("cvt.rn.bf16x2.f32 %0, %1, %2;" : "=r"(res) : "f"(b), "f"(a))
__device__ __forceinline__ float bl(uint32_t u) { return __uint_as_float(u << 16); }
__device__ __forceinline__ float bh(uint32_t u) { return __uint_as_float(u & 0xffff0000u); }
__device__ __forceinline__ void hilo2(float a, float b, uint32_t& hh, uint32_t& ll) {
    PKF2(hh, a, b);
    PKF2(ll, a - bl(hh), b - bh(hh));
}

// stream one 128x64 bf16 hi/lo chunk gmem->smem via cp.async
__device__ __forceinline__ void cpa_chunk(uint32_t smb, uint32_t base,
        const __nv_bfloat16* __restrict__ gh, const __nv_bfloat16* __restrict__ gl, int tid) {
#pragma unroll
    for (int i = 0; i < 2; i++) {
        int e = tid + i * 512, r = e >> 3, c = e & 7;
        uint32_t dst = smb + base + r * 144 + c * 16;
        CP_ASYNC(dst, (const char*)gh + (size_t)r * 512 + c * 16);
        CP_ASYNC(dst + 18432, (const char*)gl + (size_t)r * 512 + c * 16);
    }
}
__device__ __forceinline__ void ldreg_f(const float* __restrict__ src, float4* v, int tid) {
#pragma unroll
    for (int i = 0; i < 4; i++) {
        int e = tid + i * 512;
        v[i] = *(const float4*)(src + (size_t)(e >> 4) * CD + (e & 15) * 4);
    }
}
// regs -> smem chunk + STG fp32 q-copy + STG bf16 hi/lo to gmem
__device__ __forceinline__ void sts_f(char* sm, uint32_t base, const float4* v, int tid,
                                      float* __restrict__ ocopy,
                                      __nv_bfloat16* __restrict__ gqh, __nv_bfloat16* __restrict__ gql) {
#pragma unroll
    for (int i = 0; i < 4; i++) {
        int e = tid + i * 512, r = e >> 4, c4 = e & 15;
        float4 x = v[i];
        *(float4*)(ocopy + (size_t)r * 512 + c4 * 4) = x;
        uint2 hh, ll;
        hilo2(x.x, x.y, hh.x, ll.x);
        hilo2(x.z, x.w, hh.y, ll.y);
        uint32_t o = base + r * 144 + c4 * 8;
        *(uint2*)(sm + o) = hh;
        *(uint2*)(sm + 18432 + o) = ll;
        *(uint2*)(gqh + (size_t)r * CD + c4 * 4) = hh;
        *(uint2*)(gql + (size_t)r * CD + c4 * 4) = ll;
    }
}

// S GEMM: d += A(@qb) x B(@mb)^T, K=64, 3-pass hi/lo  (stride-144 tiles)
__device__ __forceinline__ void gemm64_nn(float d[2][4][4], uint32_t smb, uint32_t qb, uint32_t mb,
                                          int wm, int wn, int lane) {
    const int ar = lane & 15, ak = (lane >> 4) * 8;
    const int br = (lane & 7) + ((lane >> 4) & 1) * 8, bk = ((lane >> 3) & 1) * 8;
#pragma unroll
    for (int ks = 0; ks < 4; ks++) {
        int k0 = ks * 16;
        uint32_t Ah[2][4], Al[2][4], Bh[2][4], Bl[2][4];
#pragma unroll
        for (int ms = 0; ms < 2; ms++) {
            uint32_t o = smb + qb + (uint32_t)((wm * 32 + ms * 16 + ar) * 144 + (k0 + ak) * 2);
            LDM4(Ah[ms], o); LDM4(Al[ms], o + 18432);
        }
#pragma unroll
        for (int nq = 0; nq < 2; nq++) {
            uint32_t o = smb + mb + (uint32_t)((wn * 32 + nq * 16 + br) * 144 + (k0 + bk) * 2);
            LDM4(Bh[nq], o); LDM4(Bl[nq], o + 18432);
        }
#pragma unroll
        for (int ms = 0; ms < 2; ms++)
#pragma unroll
            for (int nq = 0; nq < 2; nq++) {
                MMA(d[ms][2*nq],   Ah[ms], Bh[nq][0], Bh[nq][1]);
                MMA(d[ms][2*nq+1], Ah[ms], Bh[nq][2], Bh[nq][3]);
                MMA(d[ms][2*nq],   Ah[ms], Bl[nq][0], Bl[nq][1]);
                MMA(d[ms][2*nq+1], Ah[ms], Bl[nq][2], Bl[nq][3]);
                MMA(d[ms][2*nq],   Al[ms], Bh[nq][0], Bh[nq][1]);
                MMA(d[ms][2*nq+1], Al[ms], Bh[nq][2], Bh[nq][3]);
            }
    }
}
// phase1 D: d2 += P^T(trans @PH_) x Q(trans @qb), K=128
__device__ __forceinline__ void gemm_tt2(float d2[2][2][4], uint32_t smb, uint32_t qb,
                                         int wm, int wn, int lane) {
    const int ar = (lane & 7) + (lane >> 4) * 8, am = ((lane >> 3) & 1) * 8;
    const int br = lane & 15, bc = (lane >> 4) * 8;
#pragma unroll
    for (int ks = 0; ks < 8; ks++) {
        int k0 = ks * 16;
        uint32_t Ah[2][4], Al[2][4], Bh[4], Bl[4];
#pragma unroll
        for (int ms = 0; ms < 2; ms++) {
            uint32_t o = smb + PH_ + (uint32_t)((k0 + ar) * 272 + (wm * 32 + ms * 16 + am) * 2);
            LDM4T(Ah[ms], o); LDM4T(Al[ms], o + 34816);
        }
        {
            uint32_t o = smb + qb + (uint32_t)((k0 + br) * 144 + (wn * 16 + bc) * 2);
            LDM4T(Bh, o); LDM4T(Bl, o + 18432);
        }
#pragma unroll
        for (int ms = 0; ms < 2; ms++) {
            MMA(d2[ms][0], Ah[ms], Bh[0], Bh[1]);
            MMA(d2[ms][1], Ah[ms], Bh[2], Bh[3]);
            MMA(d2[ms][0], Ah[ms], Bl[0], Bl[1]);
            MMA(d2[ms][1], Ah[ms], Bl[2], Bl[3]);
            MMA(d2[ms][0], Al[ms], Bh[0], Bh[1]);
            MMA(d2[ms][1], Al[ms], Bh[2], Bh[3]);
        }
    }
}
// phase2 D: d2 += P(non-trans @PH_) x nm^T(trans @mb), K=128
__device__ __forceinline__ void gemm_nt2(float d2[2][2][4], uint32_t smb, uint32_t mb,
                                         int wm, int wn, int lane) {
    const int ar = lane & 15, ak = (lane >> 4) * 8;
    const int br = lane & 15, bc = (lane >> 4) * 8;
#pragma unroll
    for (int ks = 0; ks < 8; ks++) {
        int k0 = ks * 16;
        uint32_t Ah[2][4], Al[2][4], Bh[4], Bl[4];
#pragma unroll
        for (int ms = 0; ms < 2; ms++) {
            uint32_t o = smb + PH_ + (uint32_t)((wm * 32 + ms * 16 + ar) * 272 + (k0 + ak) * 2);
            LDM4(Ah[ms], o); LDM4(Al[ms], o + 34816);
        }
        {
            uint32_t o = smb + mb + (uint32_t)((k0 + br) * 144 + (wn * 16 + bc) * 2);
            LDM4T(Bh, o); LDM4T(Bl, o + 18432);
        }
#pragma unroll
        for (int ms = 0; ms < 2; ms++) {
            MMA(d2[ms][0], Ah[ms], Bh[0], Bh[1]);
            MMA(d2[ms][1], Ah[ms], Bh[2], Bh[3]);
            MMA(d2[ms][0], Ah[ms], Bl[0], Bl[1]);
            MMA(d2[ms][1], Ah[ms], Bl[2], Bl[3]);
            MMA(d2[ms][0], Al[ms], Bh[0], Bh[1]);
            MMA(d2[ms][1], Al[ms], Bh[2], Bh[3]);
        }
    }
}

__global__ void __launch_bounds__(256) mprep_kernel(const float* __restrict__ mem) {
    int e = blockIdx.x * 256 + threadIdx.x;
    int r = e >> 6, c4 = e & 63;
    float4 v = *(const float4*)(mem + (size_t)r * CD + c4 * 4);
    uint2 hh, ll;
    hilo2(v.x, v.y, hh.x, ll.x);
    hilo2(v.z, v.w, hh.y, ll.y);
    size_t d = (size_t)r * CD + c4 * 4;
    *(uint2*)(g_m_h + d) = hh;
    *(uint2*)(g_m_l + d) = ll;
    *(float4*)(g_add_mem + (size_t)e * 4) = make_float4(0.f, 0.f, 0.f, 0.f);
}

__global__ void __launch_bounds__(512, 1)
phase1_kernel(const float* __restrict__ q, float* __restrict__ out) {
    extern __shared__ char sm[];
    const uint32_t smb = smem_u32(sm);
    const int tid = threadIdx.x, lane = tid & 31, w = tid >> 5;
    const int wm = w >> 2, wn = w & 3, lr = lane >> 2, lq = lane & 3;
    const int row0 = blockIdx.x * 128;
    float* smx = (float*)(sm + SMX);
    float* ssu = (float*)(sm + SSUM);
    __nv_bfloat16* qh = g_q_h + (size_t)row0 * CD;
    __nv_bfloat16* ql = g_q_l + (size_t)row0 * CD;
    float* ocopy = out + (size_t)row0 * 512;

    float d[2][4][4];
#pragma unroll
    for (int a = 0; a < 2; a++)
#pragma unroll
        for (int b = 0; b < 4; b++)
#pragma unroll
            for (int c = 0; c < 4; c++) d[a][b][c] = 0.0f;

    // ---- S = Q @ mem^T: Q staged into 4 RESIDENT chunks; mem streamed through SB0/SB1 ----
    float4 va[4];
    ldreg_f(q + (size_t)row0 * CD, va, tid);
    cpa_chunk(smb, SB0, g_m_h, g_m_l, tid);
    CP_COMMIT();
    sts_f(sm, RES(0), va, tid, ocopy, qh, ql);
    for (int kc = 0; kc < 4; kc++) {
        if (kc < 3) ldreg_f(q + (size_t)row0 * CD + (kc + 1) * 64, va, tid);
        __syncthreads();   // guard SB buffer reuse
        if (kc < 3) {
            cpa_chunk(smb, ((kc + 1) & 1) ? SB1 : SB0, g_m_h + (kc + 1) * 64, g_m_l + (kc + 1) * 64, tid);
            CP_COMMIT(); CP_WAIT1();
        } else CP_WAIT0();
        __syncthreads();
        gemm64_nn(d, smb, RES(kc), (kc & 1) ? SB1 : SB0, wm, wn, lane);
        if (kc < 3)
            sts_f(sm, RES(kc + 1), va, tid,
                  ocopy + (kc + 1) * 64, qh + (kc + 1) * 64, ql + (kc + 1) * 64);
    }

    // ---- fragment softmax ----
    float inv2[2][2];
#pragma unroll
    for (int ms = 0; ms < 2; ms++)
#pragma unroll
        for (int rh = 0; rh < 2; rh++) {
            float m_ = -1e30f;
#pragma unroll
            for (int nt = 0; nt < 4; nt++) m_ = fmaxf(m_, fmaxf(d[ms][nt][rh*2], d[ms][nt][rh*2+1]));
            m_ = fmaxf(m_, __shfl_xor_sync(~0u, m_, 1));
            m_ = fmaxf(m_, __shfl_xor_sync(~0u, m_, 2));
            if (lq == 0) smx[(wm*32 + ms*16 + lr + rh*8) * 4 + wn] = m_;
        }
    __syncthreads();
#pragma unroll
    for (int ms = 0; ms < 2; ms++)
#pragma unroll
        for (int rh = 0; rh < 2; rh++) {
            int r = wm*32 + ms*16 + lr + rh*8;
            float m_ = fmaxf(fmaxf(smx[r*4], smx[r*4+1]), fmaxf(smx[r*4+2], smx[r*4+3]));
            float s = 0.0f;
#pragma unroll
            for (int nt = 0; nt < 4; nt++) {
                d[ms][nt][rh*2] = __expf(d[ms][nt][rh*2] - m_);
                d[ms][nt][rh*2+1] = __expf(d[ms][nt][rh*2+1] - m_);
                s += d[ms][nt][rh*2] + d[ms][nt][rh*2+1];
            }
            s += __shfl_xor_sync(~0u, s, 1);
            s += __shfl_xor_sync(~0u, s, 2);
            if (lq == 0) ssu[r*4 + wn] = s;
        }
    __syncthreads();
#pragma unroll
    for (int ms = 0; ms < 2; ms++)
#pragma unroll
        for (int rh = 0; rh < 2; rh++) {
            int r = wm*32 + ms*16 + lr + rh*8;
            inv2[ms][rh] = 1.0f / (ssu[r*4] + ssu[r*4+1] + ssu[r*4+2] + ssu[r*4+3]);
        }
    // P tiles overlay the SB/mem region (S gemms drained by softmax barriers)
#pragma unroll
    for (int ms = 0; ms < 2; ms++)
#pragma unroll
        for (int rh = 0; rh < 2; rh++) {
            int r = wm*32 + ms*16 + lr + rh*8;
#pragma unroll
            for (int nt = 0; nt < 4; nt++) {
                int c = wn*32 + nt*8 + lq*2;
                float p0 = fmaxf(d[ms][nt][rh*2] * inv2[ms][rh], 1e-8f);
                float p1 = fmaxf(d[ms][nt][rh*2+1] * inv2[ms][rh], 1e-8f);
                uint32_t hh, ll;
                hilo2(p0, p1, hh, ll);
                *(uint32_t*)(sm + PH_ + r*272 + c*2) = hh;
                *(uint32_t*)(sm + PL_ + r*272 + c*2) = ll;
            }
        }
    __syncthreads();   // P visible to all warps

    // ---- add_mem += P^T @ Q: ZERO loads, ZERO further barriers (P + Q resident) ----
    for (int cc = 0; cc < 4; cc++) {
        float d2[2][2][4];
#pragma unroll
        for (int a = 0; a < 2; a++)
#pragma unroll
            for (int b = 0; b < 2; b++)
#pragma unroll
                for (int c = 0; c < 4; c++) d2[a][b][c] = 0.0f;
        gemm_tt2(d2, smb, RES(cc), wm, wn, lane);
#pragma unroll
        for (int ms = 0; ms < 2; ms++)
#pragma unroll
            for (int nh = 0; nh < 2; nh++) {
                int m = wm*32 + ms*16 + lr;
                int c = cc*64 + wn*16 + nh*8 + lq*2;
                atomicAdd(&g_add_mem[m*CD + c], d2[ms][nh][0]);
                atomicAdd(&g_add_mem[m*CD + c + 1], d2[ms][nh][1]);
                atomicAdd(&g_add_mem[(m+8)*CD + c], d2[ms][nh][2]);
                atomicAdd(&g_add_mem[(m+8)*CD + c + 1], d2[ms][nh][3]);
            }
    }
}

__global__ void __launch_bounds__(256)
gate_kernel(const float* __restrict__ mem, const float* __restrict__ U_w, const float* __restrict__ U_b,
            const float* __restrict__ W_w, const float* __restrict__ W_b, float* __restrict__ out_nm) {
    __shared__ float mrow[CD], arow[CD], red[256];
    const int m = blockIdx.x, tid = threadIdx.x, lane = tid & 31, wid = tid >> 5;
    mrow[tid] = mem[(size_t)m * CD + tid];
    arow[tid] = g_add_mem[(size_t)m * CD + tid];
    __syncthreads();
    float myacc = 0.0f;
#pragma unroll 4
    for (int cc = 0; cc < 32; cc++) {
        int c = wid * 32 + cc;
        const float* uw = U_w + (size_t)c * CD;
        const float* ww = W_w + (size_t)c * CD;
        float acc = 0.0f;
#pragma unroll
        for (int j = 0; j < 8; j++) {
            int k = lane + j * 32;
            acc = fmaf(mrow[k], uw[k], fmaf(arow[k], ww[k], acc));
        }
#pragma unroll
        for (int o = 16; o >= 1; o >>= 1) acc += __shfl_xor_sync(~0u, acc, o);
        if (lane == cc) myacc = acc;
    }
    const int c = tid;
    myacc += U_b[c] + W_b[c];
    float g = 1.0f / (1.0f + __expf(-myacc));
    float nm = 0.9f * mrow[c] + 0.1f * ((1.0f - g) * mrow[c] + g * arow[c]);
    red[c] = nm * nm; __syncthreads();
    for (int s = 128; s > 0; s >>= 1) { if (c < s) red[c] += red[c + s]; __syncthreads(); }
    float v = nm / fmaxf(sqrtf(red[0]), 1e-12f);
    out_nm[(size_t)m * CD + c] = v;
    __nv_bfloat16 h = __float2bfloat16(v);
    g_nm_h[(size_t)m * CD + c] = h;
    g_nm_l[(size_t)m * CD + c] = __float2bfloat16(v - __bfloat162float(h));
}

__global__ void __launch_bounds__(512, 1)
phase2_kernel(float* __restrict__ out, float* __restrict__ attn_out) {
    extern __shared__ char sm[];
    const uint32_t smb = smem_u32(sm);
    const int tid = threadIdx.x, lane = tid & 31, w = tid >> 5;
    const int wm = w >> 2, wn = w & 3, lr = lane >> 2, lq = lane & 3;
    const int row0 = blockIdx.x * 128;
    float* smx = (float*)(sm + SMX);
    float* ssu = (float*)(sm + SSUM);
    const __nv_bfloat16* qh = g_q_h + (size_t)row0 * CD;
    const __nv_bfloat16* ql = g_q_l + (size_t)row0 * CD;

    float d[2][4][4];
#pragma unroll
    for (int a = 0; a < 2; a++)
#pragma unroll
        for (int b = 0; b < 4; b++)
#pragma unroll
            for (int c = 0; c < 4; c++) d[a][b][c] = 0.0f;

    // ---- load nm into 4 RESIDENT chunks (one group); Q streams through SB0/SB1 ----
    for (int k = 0; k < 4; k++)
        cpa_chunk(smb, RES(k), g_nm_h + k * 64, g_nm_l + k * 64, tid);
    CP_COMMIT();
    cpa_chunk(smb, SB0, qh, ql, tid);
    CP_COMMIT();
    for (int kc = 0; kc < 4; kc++) {
        __syncthreads();   // guard SB buffer reuse
        if (kc < 3) {
            cpa_chunk(smb, ((kc + 1) & 1) ? SB1 : SB0, qh + (kc + 1) * 64, ql + (kc + 1) * 64, tid);
            CP_COMMIT(); CP_WAIT1();
        } else CP_WAIT0();
        __syncthreads();
        gemm64_nn(d, smb, (kc & 1) ? SB1 : SB0, RES(kc), wm, wn, lane);
    }

    // ---- softmax -> hard-shrink -> L1 norm ----
    float inv2[2][2];
#pragma unroll
    for (int ms = 0; ms < 2; ms++)
#pragma unroll
        for (int rh = 0; rh < 2; rh++) {
            float m_ = -1e30f;
#pragma unroll
            for (int nt = 0; nt < 4; nt++) m_ = fmaxf(m_, fmaxf(d[ms][nt][rh*2], d[ms][nt][rh*2+1]));
            m_ = fmaxf(m_, __shfl_xor_sync(~0u, m_, 1));
            m_ = fmaxf(m_, __shfl_xor_sync(~0u, m_, 2));
            if (lq == 0) smx[(wm*32 + ms*16 + lr + rh*8) * 4 + wn] = m_;
        }
    __syncthreads();
#pragma unroll
    for (int ms = 0; ms < 2; ms++)
#pragma unroll
        for (int rh = 0; rh < 2; rh++) {
            int r = wm*32 + ms*16 + lr + rh*8;
            float m_ = fmaxf(fmaxf(smx[r*4], smx[r*4+1]), fmaxf(smx[r*4+2], smx[r*4+3]));
            float s = 0.0f;
#pragma unroll
            for (int nt = 0; nt < 4; nt++) {
                d[ms][nt][rh*2] = __expf(d[ms][nt][rh*2] - m_);
                d[ms][nt][rh*2+1] = __expf(d[ms][nt][rh*2+1] - m_);
                s += d[ms][nt][rh*2] + d[ms][nt][rh*2+1];
            }
            s += __shfl_xor_sync(~0u, s, 1);
            s += __shfl_xor_sync(~0u, s, 2);
            if (lq == 0) ssu[r*4 + wn] = s;
        }
    __syncthreads();
#pragma unroll
    for (int ms = 0; ms < 2; ms++)
#pragma unroll
        for (int rh = 0; rh < 2; rh++) {
            int r = wm*32 + ms*16 + lr + rh*8;
            inv2[ms][rh] = 1.0f / (ssu[r*4] + ssu[r*4+1] + ssu[r*4+2] + ssu[r*4+3]);
        }
    __syncthreads();
#pragma unroll
    for (int ms = 0; ms < 2; ms++)
#pragma unroll
        for (int rh = 0; rh < 2; rh++) {
            int r = wm*32 + ms*16 + lr + rh*8;
            float l1 = 0.0f;
#pragma unroll
            for (int nt = 0; nt < 4; nt++)
#pragma unroll
                for (int cb = 0; cb < 2; cb++) {
                    float a = d[ms][nt][rh*2+cb] * inv2[ms][rh];
                    float dd = a - 0.0025f;
                    float a2 = fmaxf(dd, 0.0f) * a / (fabsf(dd) + 1e-12f);
                    d[ms][nt][rh*2+cb] = a2; l1 += a2;
                }
            l1 += __shfl_xor_sync(~0u, l1, 1);
            l1 += __shfl_xor_sync(~0u, l1, 2);
            if (lq == 0) smx[r*4 + wn] = l1;
        }
    __syncthreads();
    // P tiles overlay the SB/Q region (S gemms drained)
#pragma unroll
    for (int ms = 0; ms < 2; ms++)
#pragma unroll
        for (int rh = 0; rh < 2; rh++) {
            int r = wm*32 + ms*16 + lr + rh*8;
            float invl = 1.0f / fmaxf(smx[r*4] + smx[r*4+1] + smx[r*4+2] + smx[r*4+3], 1e-12f);
#pragma unroll
            for (int nt = 0; nt < 4; nt++) {
                int c = wn*32 + nt*8 + lq*2;
                uint32_t hh, ll;
                hilo2(d[ms][nt][rh*2] * invl, d[ms][nt][rh*2+1] * invl, hh, ll);
                *(uint32_t*)(sm + PH_ + r*272 + c*2) = hh;
                *(uint32_t*)(sm + PL_ + r*272 + c*2) = ll;
            }
        }
    __syncthreads();
    // attn out (hi+lo reconstruct, coalesced)
#pragma unroll
    for (int i = 0; i < 8; i++) {
        int e = tid + i * 512, r = e >> 5, m4 = e & 31;
        uint32_t o = r * 272 + m4 * 8;
        uint2 hh = *(uint2*)(sm + PH_ + o), ll = *(uint2*)(sm + PL_ + o);
        *(float4*)(attn_out + (size_t)(row0 + r) * MD + m4 * 4) =
            make_float4(bl(hh.x) + bl(ll.x), bh(hh.x) + bh(ll.x),
                        bl(hh.y) + bl(ll.y), bh(hh.y) + bh(ll.y));
    }

    // ---- add_memory = P @ nm: ZERO loads, ZERO barriers (P + nm resident) ----
    for (int cc = 0; cc < 4; cc++) {
        float d2[2][2][4];
#pragma unroll
        for (int a = 0; a < 2; a++)
#pragma unroll
            for (int b = 0; b < 2; b++)
#pragma unroll
                for (int c = 0; c < 4; c++) d2[a][b][c] = 0.0f;
        gemm_nt2(d2, smb, RES(cc), wm, wn, lane);
#pragma unroll
        for (int ms = 0; ms < 2; ms++)
#pragma unroll
            for (int nh = 0; nh < 2; nh++) {
                int r = row0 + wm*32 + ms*16 + lr;
                int c = cc*64 + wn*16 + nh*8 + lq*2;
                *(float2*)(out + (size_t)r * 512 + 256 + c) = make_float2(d2[ms][nh][0], d2[ms][nh][1]);
                *(float2*)(out + (size_t)(r + 8) * 512 + 256 + c) = make_float2(d2[ms][nh][2], d2[ms][nh][3]);
            }
    }
}

extern "C" void kernel_launch(void* const* d_in, const int* in_sizes, int n_in,
                              void* d_out, int out_size) {
    const float* q = (const float*)d_in[0];
    const float* mem = (const float*)d_in[1];
    float* out = (float*)d_out;
    cudaFuncSetAttribute(phase1_kernel, cudaFuncAttributeMaxDynamicSharedMemorySize, SMEMB);
    cudaFuncSetAttribute(phase2_kernel, cudaFuncAttributeMaxDynamicSharedMemorySize, SMEMB);
    mprep_kernel<<<32, 256>>>(mem);
    phase1_kernel<<<NB, 512, SMEMB>>>(q, out);
    gate_kernel<<<MD, 256>>>(mem, (const float*)d_in[2], (const float*)d_in[3],
                             (const float*)d_in[4], (const float*)d_in[5], out + NM_OFF);
    phase2_kernel<<<NB, 512, SMEMB>>>(out, out + ATTN_OFF);
}

// round 17
// speedup vs baseline: 1.1100x; 1.1100x over previous
#include <cuda_runtime.h>
#include <cuda_fp16.h>
#include <cstdint>

#define TT 131072
#define CD 256
#define MD 128
#define NB 1024
#define ATTN_OFF ((size_t)TT*2*CD)
#define NM_OFF (ATTN_OFF+(size_t)TT*MD)

// smem: double-buffered chunk tiles 128x64 fp16 (stride 144B), hi at base, lo at +18432
#define QB0 0u
#define QB1 36864u
#define MB0 73728u
#define MB1 110592u
// P tiles 128x128 fp16 stride 272B: phase1 over MB region, phase2 over QB region
#define P1H 73728u
#define P1L 108544u
#define P2H 0u
#define P2L 34816u
#define SMX 147456
#define SSUM 149504
#define SMEMB 151552

__device__ float g_add_mem[MD*CD];
__device__ __half g_nm_h[MD*CD], g_nm_l[MD*CD];
__device__ __half g_m_h[MD*CD], g_m_l[MD*CD];
__device__ __half g_q_h[(size_t)TT*CD], g_q_l[(size_t)TT*CD];

__device__ __forceinline__ uint32_t smem_u32(const void* p) {
    uint32_t a;
    asm("{ .reg .u64 t; cvta.to.shared.u64 t, %1; cvt.u32.u64 %0, t; }" : "=r"(a) : "l"(p));
    return a;
}
#define LDM4(r, a) asm volatile("ldmatrix.sync.aligned.m8n8.x4.shared.b16 {%0,%1,%2,%3}, [%4];" \
    : "=r"((r)[0]),"=r"((r)[1]),"=r"((r)[2]),"=r"((r)[3]) : "r"(a))
#define LDM4T(r, a) asm volatile("ldmatrix.sync.aligned.m8n8.x4.trans.shared.b16 {%0,%1,%2,%3}, [%4];" \
    : "=r"((r)[0]),"=r"((r)[1]),"=r"((r)[2]),"=r"((r)[3]) : "r"(a))
#define MMA(d, a, b0, b1) asm volatile( \
    "mma.sync.aligned.m16n8k16.row.col.f32.f16.f16.f32 {%0,%1,%2,%3}, {%4,%5,%6,%7}, {%8,%9}, {%0,%1,%2,%3};" \
    : "+f"((d)[0]),"+f"((d)[1]),"+f"((d)[2]),"+f"((d)[3]) \
    : "r"((a)[0]),"r"((a)[1]),"r"((a)[2]),"r"((a)[3]), "r"(b0),"r"(b1))
#define CP_ASYNC(dst, src) asm volatile("cp.async.ca.shared.global [%0], [%1], 16;" :: "r"(dst), "l"(src) : "memory")
#define CP_COMMIT() asm volatile("cp.async.commit_group;" ::: "memory")
#define CP_WAIT1() asm volatile("cp.async.wait_group 1;" ::: "memory")
#define CP_WAIT0() asm volatile("cp.async.wait_group 0;" ::: "memory")

#define PKH2(res, a, b) asm("cvt.rn.f16x2.f32 %0, %1, %2;" : "=r"(res) : "f"(b), "f"(a))
__device__ __forceinline__ float f16lo(uint32_t u) { return __half2float(__ushort_as_half((unsigned short)u)); }
__device__ __forceinline__ float f16hi(uint32_t u) { return __half2float(__ushort_as_half((unsigned short)(u >> 16))); }
__device__ __forceinline__ void hilo2h(float a, float b, uint32_t& hh, uint32_t& ll) {
    PKH2(hh, a, b);
    PKH2(ll, a - f16lo(hh), b - f16hi(hh));
}

// stream one 128x64 fp16 hi/lo chunk gmem->smem via cp.async (4 ops/thread)
__device__ __forceinline__ void cpa_hl(uint32_t smb, uint32_t base,
        const __half* __restrict__ gh, const __half* __restrict__ gl, int tid) {
#pragma unroll
    for (int i = 0; i < 2; i++) {
        int e = tid + i * 512, r = e >> 3, c = e & 7;
        uint32_t dst = smb + base + r * 144 + c * 16;
        CP_ASYNC(dst, (const char*)gh + (size_t)r * 512 + c * 16);
        CP_ASYNC(dst + 18432, (const char*)gl + (size_t)r * 512 + c * 16);
    }
}
// stream one 128x64 fp16 single-plane chunk (2 ops/thread)
__device__ __forceinline__ void cpa_s(uint32_t smb, uint32_t base,
        const __half* __restrict__ g, int tid) {
#pragma unroll
    for (int i = 0; i < 2; i++) {
        int e = tid + i * 512, r = e >> 3, c = e & 7;
        CP_ASYNC(smb + base + r * 144 + c * 16, (const char*)g + (size_t)r * 512 + c * 16);
    }
}
__device__ __forceinline__ void ldreg_f(const float* __restrict__ src, float4* v, int tid) {
#pragma unroll
    for (int i = 0; i < 4; i++) {
        int e = tid + i * 512;
        v[i] = *(const float4*)(src + (size_t)(e >> 4) * CD + (e & 15) * 4);
    }
}
// regs -> smem fp16 hi/lo tiles + STG fp32 q-copy + STG fp16 hi/lo to gmem
__device__ __forceinline__ void sts_f(char* sm, uint32_t base, const float4* v, int tid,
                                      float* __restrict__ ocopy,
                                      __half* __restrict__ gqh, __half* __restrict__ gql) {
#pragma unroll
    for (int i = 0; i < 4; i++) {
        int e = tid + i * 512, r = e >> 4, c4 = e & 15;
        float4 x = v[i];
        *(float4*)(ocopy + (size_t)r * 512 + c4 * 4) = x;
        uint2 hh, ll;
        hilo2h(x.x, x.y, hh.x, ll.x);
        hilo2h(x.z, x.w, hh.y, ll.y);
        uint32_t o = base + r * 144 + c4 * 8;
        *(uint2*)(sm + o) = hh;
        *(uint2*)(sm + 18432 + o) = ll;
        *(uint2*)(gqh + (size_t)r * CD + c4 * 4) = hh;
        *(uint2*)(gql + (size_t)r * CD + c4 * 4) = ll;
    }
}

// S GEMM: 3-pass (A hi/lo x B hi/lo: hh + hl + lh), K=64
__device__ __forceinline__ void gemm64_nn(float d[2][4][4], uint32_t smb, uint32_t qb, uint32_t mb,
                                          int wm, int wn, int lane) {
    const int ar = lane & 15, ak = (lane >> 4) * 8;
    const int br = (lane & 7) + ((lane >> 4) & 1) * 8, bk = ((lane >> 3) & 1) * 8;
#pragma unroll
    for (int ks = 0; ks < 4; ks++) {
        int k0 = ks * 16;
        uint32_t Ah[2][4], Al[2][4], Bh[2][4], Bl[2][4];
#pragma unroll
        for (int ms = 0; ms < 2; ms++) {
            uint32_t o = smb + qb + (uint32_t)((wm * 32 + ms * 16 + ar) * 144 + (k0 + ak) * 2);
            LDM4(Ah[ms], o); LDM4(Al[ms], o + 18432);
        }
#pragma unroll
        for (int nq = 0; nq < 2; nq++) {
            uint32_t o = smb + mb + (uint32_t)((wn * 32 + nq * 16 + br) * 144 + (k0 + bk) * 2);
            LDM4(Bh[nq], o); LDM4(Bl[nq], o + 18432);
        }
#pragma unroll
        for (int ms = 0; ms < 2; ms++)
#pragma unroll
            for (int nq = 0; nq < 2; nq++) {
                MMA(d[ms][2*nq],   Ah[ms], Bh[nq][0], Bh[nq][1]);
                MMA(d[ms][2*nq+1], Ah[ms], Bh[nq][2], Bh[nq][3]);
                MMA(d[ms][2*nq],   Ah[ms], Bl[nq][0], Bl[nq][1]);
                MMA(d[ms][2*nq+1], Ah[ms], Bl[nq][2], Bl[nq][3]);
                MMA(d[ms][2*nq],   Al[ms], Bh[nq][0], Bh[nq][1]);
                MMA(d[ms][2*nq+1], Al[ms], Bh[nq][2], Bh[nq][3]);
            }
    }
}
// phase1 D: 2-pass — P^T(trans hi/lo) x q_hi(trans single @qb), K=128
__device__ __forceinline__ void gemm_tt2(float d2[2][2][4], uint32_t smb, uint32_t qb,
                                         int wm, int wn, int lane) {
    const int ar = (lane & 7) + (lane >> 4) * 8, am = ((lane >> 3) & 1) * 8;
    const int br = lane & 15, bc = (lane >> 4) * 8;
#pragma unroll
    for (int ks = 0; ks < 8; ks++) {
        int k0 = ks * 16;
        uint32_t Ah[2][4], Al[2][4], B[4];
#pragma unroll
        for (int ms = 0; ms < 2; ms++) {
            uint32_t o = smb + P1H + (uint32_t)((k0 + ar) * 272 + (wm * 32 + ms * 16 + am) * 2);
            LDM4T(Ah[ms], o); LDM4T(Al[ms], o + 34816);
        }
        LDM4T(B, smb + qb + (uint32_t)((k0 + br) * 144 + (wn * 16 + bc) * 2));
#pragma unroll
        for (int ms = 0; ms < 2; ms++) {
            MMA(d2[ms][0], Ah[ms], B[0], B[1]);
            MMA(d2[ms][1], Ah[ms], B[2], B[3]);
            MMA(d2[ms][0], Al[ms], B[0], B[1]);
            MMA(d2[ms][1], Al[ms], B[2], B[3]);
        }
    }
}
// phase2 D: 2-pass — P(non-trans hi/lo) x nm_hi^T(trans single @mb), K=128
__device__ __forceinline__ void gemm_nt2(float d2[2][2][4], uint32_t smb, uint32_t mb,
                                         int wm, int wn, int lane) {
    const int ar = lane & 15, ak = (lane >> 4) * 8;
    const int br = lane & 15, bc = (lane >> 4) * 8;
#pragma unroll
    for (int ks = 0; ks < 8; ks++) {
        int k0 = ks * 16;
        uint32_t Ah[2][4], Al[2][4], B[4];
#pragma unroll
        for (int ms = 0; ms < 2; ms++) {
            uint32_t o = smb + P2H + (uint32_t)((wm * 32 + ms * 16 + ar) * 272 + (k0 + ak) * 2);
            LDM4(Ah[ms], o); LDM4(Al[ms], o + 34816);
        }
        LDM4T(B, smb + mb + (uint32_t)((k0 + br) * 144 + (wn * 16 + bc) * 2));
#pragma unroll
        for (int ms = 0; ms < 2; ms++) {
            MMA(d2[ms][0], Ah[ms], B[0], B[1]);
            MMA(d2[ms][1], Ah[ms], B[2], B[3]);
            MMA(d2[ms][0], Al[ms], B[0], B[1]);
            MMA(d2[ms][1], Al[ms], B[2], B[3]);
        }
    }
}

// mem -> m_h/m_l fp16 + zero add_mem
__global__ void __launch_bounds__(256) mprep_kernel(const float* __restrict__ mem) {
    int e = blockIdx.x * 256 + threadIdx.x;
    int r = e >> 6, c4 = e & 63;
    float4 v = *(const float4*)(mem + (size_t)r * CD + c4 * 4);
    uint2 hh, ll;
    hilo2h(v.x, v.y, hh.x, ll.x);
    hilo2h(v.z, v.w, hh.y, ll.y);
    size_t d = (size_t)r * CD + c4 * 4;
    *(uint2*)(g_m_h + d) = hh;
    *(uint2*)(g_m_l + d) = ll;
    *(float4*)(g_add_mem + (size_t)e * 4) = make_float4(0.f, 0.f, 0.f, 0.f);
}

__global__ void __launch_bounds__(512, 1)
phase1_kernel(const float* __restrict__ q, float* __restrict__ out) {
    extern __shared__ char sm[];
    const uint32_t smb = smem_u32(sm);
    const int tid = threadIdx.x, lane = tid & 31, w = tid >> 5;
    const int wm = w >> 2, wn = w & 3, lr = lane >> 2, lq = lane & 3;
    const int row0 = blockIdx.x * 128;
    float* smx = (float*)(sm + SMX);
    float* ssu = (float*)(sm + SSUM);
    __half* qh = g_q_h + (size_t)row0 * CD;
    __half* ql = g_q_l + (size_t)row0 * CD;
    float* ocopy = out + (size_t)row0 * 512;

    float d[2][4][4];
#pragma unroll
    for (int a = 0; a < 2; a++)
#pragma unroll
        for (int b = 0; b < 4; b++)
#pragma unroll
            for (int c = 0; c < 4; c++) d[a][b][c] = 0.0f;

    // ---- S = Q @ mem^T; Q staged from fp32 (writes q-copy + fp16 hi/lo), mem hi/lo via cp.async ----
    float4 va[4];
    ldreg_f(q + (size_t)row0 * CD, va, tid);
    cpa_hl(smb, MB0, g_m_h, g_m_l, tid);
    CP_COMMIT();
    sts_f(sm, QB0, va, tid, ocopy, qh, ql);
    for (int kc = 0; kc < 4; kc++) {
        if (kc < 3) ldreg_f(q + (size_t)row0 * CD + (kc + 1) * 64, va, tid);
        __syncthreads();   // guard buffer reuse
        if (kc < 3) {
            cpa_hl(smb, ((kc + 1) & 1) ? MB1 : MB0, g_m_h + (kc + 1) * 64, g_m_l + (kc + 1) * 64, tid);
            CP_COMMIT(); CP_WAIT1();
        } else CP_WAIT0();
        __syncthreads();   // cp.async + sts_f visible
        gemm64_nn(d, smb, (kc & 1) ? QB1 : QB0, (kc & 1) ? MB1 : MB0, wm, wn, lane);
        if (kc < 3)
            sts_f(sm, ((kc + 1) & 1) ? QB1 : QB0, va, tid,
                  ocopy + (kc + 1) * 64, qh + (kc + 1) * 64, ql + (kc + 1) * 64);
    }

    // ---- fragment softmax ----
    float inv2[2][2];
#pragma unroll
    for (int ms = 0; ms < 2; ms++)
#pragma unroll
        for (int rh = 0; rh < 2; rh++) {
            float m_ = -1e30f;
#pragma unroll
            for (int nt = 0; nt < 4; nt++) m_ = fmaxf(m_, fmaxf(d[ms][nt][rh*2], d[ms][nt][rh*2+1]));
            m_ = fmaxf(m_, __shfl_xor_sync(~0u, m_, 1));
            m_ = fmaxf(m_, __shfl_xor_sync(~0u, m_, 2));
            if (lq == 0) smx[(wm*32 + ms*16 + lr + rh*8) * 4 + wn] = m_;
        }
    __syncthreads();
#pragma unroll
    for (int ms = 0; ms < 2; ms++)
#pragma unroll
        for (int rh = 0; rh < 2; rh++) {
            int r = wm*32 + ms*16 + lr + rh*8;
            float m_ = fmaxf(fmaxf(smx[r*4], smx[r*4+1]), fmaxf(smx[r*4+2], smx[r*4+3]));
            float s = 0.0f;
#pragma unroll
            for (int nt = 0; nt < 4; nt++) {
                d[ms][nt][rh*2] = __expf(d[ms][nt][rh*2] - m_);
                d[ms][nt][rh*2+1] = __expf(d[ms][nt][rh*2+1] - m_);
                s += d[ms][nt][rh*2] + d[ms][nt][rh*2+1];
            }
            s += __shfl_xor_sync(~0u, s, 1);
            s += __shfl_xor_sync(~0u, s, 2);
            if (lq == 0) ssu[r*4 + wn] = s;
        }
    __syncthreads();
#pragma unroll
    for (int ms = 0; ms < 2; ms++)
#pragma unroll
        for (int rh = 0; rh < 2; rh++) {
            int r = wm*32 + ms*16 + lr + rh*8;
            inv2[ms][rh] = 1.0f / (ssu[r*4] + ssu[r*4+1] + ssu[r*4+2] + ssu[r*4+3]);
        }
    // P tiles (fp16 hi/lo) over MB region (S gemms drained by softmax barriers)
#pragma unroll
    for (int ms = 0; ms < 2; ms++)
#pragma unroll
        for (int rh = 0; rh < 2; rh++) {
            int r = wm*32 + ms*16 + lr + rh*8;
#pragma unroll
            for (int nt = 0; nt < 4; nt++) {
                int c = wn*32 + nt*8 + lq*2;
                float p0 = fmaxf(d[ms][nt][rh*2] * inv2[ms][rh], 1e-8f);
                float p1 = fmaxf(d[ms][nt][rh*2+1] * inv2[ms][rh], 1e-8f);
                uint32_t hh, ll;
                hilo2h(p0, p1, hh, ll);
                *(uint32_t*)(sm + P1H + r*272 + c*2) = hh;
                *(uint32_t*)(sm + P1L + r*272 + c*2) = ll;
            }
        }
    // first D-loop chunk: q_hi single into QB0 (S loop drained)
    cpa_s(smb, QB0, qh, tid);
    CP_COMMIT();

    // ---- add_mem += P^T @ q_hi (single-plane streamed through QB) ----
    for (int cc = 0; cc < 4; cc++) {
        __syncthreads();   // guard buffer reuse + P visibility
        if (cc < 3) {
            cpa_s(smb, ((cc + 1) & 1) ? QB1 : QB0, qh + (cc + 1) * 64, tid);
            CP_COMMIT(); CP_WAIT1();
        } else CP_WAIT0();
        __syncthreads();
        float d2[2][2][4];
#pragma unroll
        for (int a = 0; a < 2; a++)
#pragma unroll
            for (int b = 0; b < 2; b++)
#pragma unroll
                for (int c = 0; c < 4; c++) d2[a][b][c] = 0.0f;
        gemm_tt2(d2, smb, (cc & 1) ? QB1 : QB0, wm, wn, lane);
#pragma unroll
        for (int ms = 0; ms < 2; ms++)
#pragma unroll
            for (int nh = 0; nh < 2; nh++) {
                int m = wm*32 + ms*16 + lr;
                int c = cc*64 + wn*16 + nh*8 + lq*2;
                atomicAdd(&g_add_mem[m*CD + c], d2[ms][nh][0]);
                atomicAdd(&g_add_mem[m*CD + c + 1], d2[ms][nh][1]);
                atomicAdd(&g_add_mem[(m+8)*CD + c], d2[ms][nh][2]);
                atomicAdd(&g_add_mem[(m+8)*CD + c + 1], d2[ms][nh][3]);
            }
    }
}

__global__ void __launch_bounds__(256)
gate_kernel(const float* __restrict__ mem, const float* __restrict__ U_w, const float* __restrict__ U_b,
            const float* __restrict__ W_w, const float* __restrict__ W_b, float* __restrict__ out_nm) {
    __shared__ float mrow[CD], arow[CD], red[256];
    const int m = blockIdx.x, tid = threadIdx.x, lane = tid & 31, wid = tid >> 5;
    mrow[tid] = mem[(size_t)m * CD + tid];
    arow[tid] = g_add_mem[(size_t)m * CD + tid];
    __syncthreads();
    float myacc = 0.0f;
#pragma unroll 4
    for (int cc = 0; cc < 32; cc++) {
        int c = wid * 32 + cc;
        const float* uw = U_w + (size_t)c * CD;
        const float* ww = W_w + (size_t)c * CD;
        float acc = 0.0f;
#pragma unroll
        for (int j = 0; j < 8; j++) {
            int k = lane + j * 32;
            acc = fmaf(mrow[k], uw[k], fmaf(arow[k], ww[k], acc));
        }
#pragma unroll
        for (int o = 16; o >= 1; o >>= 1) acc += __shfl_xor_sync(~0u, acc, o);
        if (lane == cc) myacc = acc;
    }
    const int c = tid;
    myacc += U_b[c] + W_b[c];
    float g = 1.0f / (1.0f + __expf(-myacc));
    float nm = 0.9f * mrow[c] + 0.1f * ((1.0f - g) * mrow[c] + g * arow[c]);
    red[c] = nm * nm; __syncthreads();
    for (int s = 128; s > 0; s >>= 1) { if (c < s) red[c] += red[c + s]; __syncthreads(); }
    float v = nm / fmaxf(sqrtf(red[0]), 1e-12f);
    out_nm[(size_t)m * CD + c] = v;
    __half h = __float2half_rn(v);
    g_nm_h[(size_t)m * CD + c] = h;
    g_nm_l[(size_t)m * CD + c] = __float2half_rn(v - __half2float(h));
}

__global__ void __launch_bounds__(512, 1)
phase2_kernel(float* __restrict__ out, float* __restrict__ attn_out) {
    extern __shared__ char sm[];
    const uint32_t smb = smem_u32(sm);
    const int tid = threadIdx.x, lane = tid & 31, w = tid >> 5;
    const int wm = w >> 2, wn = w & 3, lr = lane >> 2, lq = lane & 3;
    const int row0 = blockIdx.x * 128;
    float* smx = (float*)(sm + SMX);
    float* ssu = (float*)(sm + SSUM);
    const __half* qh = g_q_h + (size_t)row0 * CD;
    const __half* ql = g_q_l + (size_t)row0 * CD;

    float d[2][4][4];
#pragma unroll
    for (int a = 0; a < 2; a++)
#pragma unroll
        for (int b = 0; b < 4; b++)
#pragma unroll
            for (int c = 0; c < 4; c++) d[a][b][c] = 0.0f;

    // ---- S = Q @ nm^T: both hi/lo, cp.async double-buffered ----
    cpa_hl(smb, QB0, qh, ql, tid);
    cpa_hl(smb, MB0, g_nm_h, g_nm_l, tid);
    CP_COMMIT();
    for (int kc = 0; kc < 4; kc++) {
        __syncthreads();   // guard buffer reuse
        if (kc < 3) {
            cpa_hl(smb, ((kc + 1) & 1) ? QB1 : QB0, qh + (kc + 1) * 64, ql + (kc + 1) * 64, tid);
            cpa_hl(smb, ((kc + 1) & 1) ? MB1 : MB0, g_nm_h + (kc + 1) * 64, g_nm_l + (kc + 1) * 64, tid);
            CP_COMMIT(); CP_WAIT1();
        } else CP_WAIT0();
        __syncthreads();
        gemm64_nn(d, smb, (kc & 1) ? QB1 : QB0, (kc & 1) ? MB1 : MB0, wm, wn, lane);
    }
    // first D-loop nm_hi chunk (MB0 dead after kc=3 barriers)
    cpa_s(smb, MB0, g_nm_h, tid);
    CP_COMMIT();

    // ---- softmax -> hard-shrink -> L1 norm ----
    float inv2[2][2];
#pragma unroll
    for (int ms = 0; ms < 2; ms++)
#pragma unroll
        for (int rh = 0; rh < 2; rh++) {
            float m_ = -1e30f;
#pragma unroll
            for (int nt = 0; nt < 4; nt++) m_ = fmaxf(m_, fmaxf(d[ms][nt][rh*2], d[ms][nt][rh*2+1]));
            m_ = fmaxf(m_, __shfl_xor_sync(~0u, m_, 1));
            m_ = fmaxf(m_, __shfl_xor_sync(~0u, m_, 2));
            if (lq == 0) smx[(wm*32 + ms*16 + lr + rh*8) * 4 + wn] = m_;
        }
    __syncthreads();
#pragma unroll
    for (int ms = 0; ms < 2; ms++)
#pragma unroll
        for (int rh = 0; rh < 2; rh++) {
            int r = wm*32 + ms*16 + lr + rh*8;
            float m_ = fmaxf(fmaxf(smx[r*4], smx[r*4+1]), fmaxf(smx[r*4+2], smx[r*4+3]));
            float s = 0.0f;
#pragma unroll
            for (int nt = 0; nt < 4; nt++) {
                d[ms][nt][rh*2] = __expf(d[ms][nt][rh*2] - m_);
                d[ms][nt][rh*2+1] = __expf(d[ms][nt][rh*2+1] - m_);
                s += d[ms][nt][rh*2] + d[ms][nt][rh*2+1];
            }
            s += __shfl_xor_sync(~0u, s, 1);
            s += __shfl_xor_sync(~0u, s, 2);
            if (lq == 0) ssu[r*4 + wn] = s;
        }
    __syncthreads();
#pragma unroll
    for (int ms = 0; ms < 2; ms++)
#pragma unroll
        for (int rh = 0; rh < 2; rh++) {
            int r = wm*32 + ms*16 + lr + rh*8;
            inv2[ms][rh] = 1.0f / (ssu[r*4] + ssu[r*4+1] + ssu[r*4+2] + ssu[r*4+3]);
        }
    __syncthreads();
#pragma unroll
    for (int ms = 0; ms < 2; ms++)
#pragma unroll
        for (int rh = 0; rh < 2; rh++) {
            int r = wm*32 + ms*16 + lr + rh*8;
            float l1 = 0.0f;
#pragma unroll
            for (int nt = 0; nt < 4; nt++)
#pragma unroll
                for (int cb = 0; cb < 2; cb++) {
                    float a = d[ms][nt][rh*2+cb] * inv2[ms][rh];
                    float dd = a - 0.0025f;
                    float a2 = fmaxf(dd, 0.0f) * a / (fabsf(dd) + 1e-12f);
                    d[ms][nt][rh*2+cb] = a2; l1 += a2;
                }
            l1 += __shfl_xor_sync(~0u, l1, 1);
            l1 += __shfl_xor_sync(~0u, l1, 2);
            if (lq == 0) smx[r*4 + wn] = l1;
        }
    __syncthreads();
    // P tiles (fp16 hi/lo) over QB region (S gemms drained)
#pragma unroll
    for (int ms = 0; ms < 2; ms++)
#pragma unroll
        for (int rh = 0; rh < 2; rh++) {
            int r = wm*32 + ms*16 + lr + rh*8;
            float invl = 1.0f / fmaxf(smx[r*4] + smx[r*4+1] + smx[r*4+2] + smx[r*4+3], 1e-12f);
#pragma unroll
            for (int nt = 0; nt < 4; nt++) {
                int c = wn*32 + nt*8 + lq*2;
                uint32_t hh, ll;
                hilo2h(d[ms][nt][rh*2] * invl, d[ms][nt][rh*2+1] * invl, hh, ll);
                *(uint32_t*)(sm + P2H + r*272 + c*2) = hh;
                *(uint32_t*)(sm + P2L + r*272 + c*2) = ll;
            }
        }
    __syncthreads();
    // attn out (fp16 hi+lo reconstruct, coalesced)
#pragma unroll
    for (int i = 0; i < 8; i++) {
        int e = tid + i * 512, r = e >> 5, m4 = e & 31;
        uint32_t o = r * 272 + m4 * 8;
        uint2 hh = *(uint2*)(sm + P2H + o), ll = *(uint2*)(sm + P2L + o);
        *(float4*)(attn_out + (size_t)(row0 + r) * MD + m4 * 4) =
            make_float4(f16lo(hh.x) + f16lo(ll.x), f16hi(hh.x) + f16hi(ll.x),
                        f16lo(hh.y) + f16lo(ll.y), f16hi(hh.y) + f16hi(ll.y));
    }

    // ---- add_memory = P @ nm_hi (single-plane streamed through MB) ----
    for (int cc = 0; cc < 4; cc++) {
        __syncthreads();   // guard buffer reuse
        if (cc < 3) {
            cpa_s(smb, ((cc + 1) & 1) ? MB1 : MB0, g_nm_h + (cc + 1) * 64, tid);
            CP_COMMIT(); CP_WAIT1();
        } else CP_WAIT0();
        __syncthreads();
        float d2[2][2][4];
#pragma unroll
        for (int a = 0; a < 2; a++)
#pragma unroll
            for (int b = 0; b < 2; b++)
#pragma unroll
                for (int c = 0; c < 4; c++) d2[a][b][c] = 0.0f;
        gemm_nt2(d2, smb, (cc & 1) ? MB1 : MB0, wm, wn, lane);
#pragma unroll
        for (int ms = 0; ms < 2; ms++)
#pragma unroll
            for (int nh = 0; nh < 2; nh++) {
                int r = row0 + wm*32 + ms*16 + lr;
                int c = cc*64 + wn*16 + nh*8 + lq*2;
                *(float2*)(out + (size_t)r * 512 + 256 + c) = make_float2(d2[ms][nh][0], d2[ms][nh][1]);
                *(float2*)(out + (size_t)(r + 8) * 512 + 256 + c) = make_float2(d2[ms][nh][2], d2[ms][nh][3]);
            }
    }
}

extern "C" void kernel_launch(void* const* d_in, const int* in_sizes, int n_in,
                              void* d_out, int out_size) {
    const float* q = (const float*)d_in[0];
    const float* mem = (const float*)d_in[1];
    float* out = (float*)d_out;
    cudaFuncSetAttribute(phase1_kernel, cudaFuncAttributeMaxDynamicSharedMemorySize, SMEMB);
    cudaFuncSetAttribute(phase2_kernel, cudaFuncAttributeMaxDynamicSharedMemorySize, SMEMB);
    mprep_kernel<<<32, 256>>>(mem);
    phase1_kernel<<<NB, 512, SMEMB>>>(q, out);
    gate_kernel<<<MD, 256>>>(mem, (const float*)d_in[2], (const float*)d_in[3],
                             (const float*)d_in[4], (const float*)d_in[5], out + NM_OFF);
    phase2_kernel<<<NB, 512, SMEMB>>>(out, out + ATTN_OFF);
}